// round 6
// baseline (speedup 1.0000x reference)
#include <cuda_runtime.h>
#include <cstdint>

#define N_NODES 500000
#define N_EDGES 1250000
#define IN_DIM  128
#define HID     64
#define N_GRAPHS 16384

typedef unsigned long long ull;

// ---- scratch (static device globals: allocation-free rule) ----
__device__ float g_y  [(size_t)N_NODES * HID];
__device__ float g_agg[(size_t)N_NODES * HID];
__device__ float g_h  [(size_t)N_NODES * HID];
__device__ int   g_src[N_EDGES];
__device__ int   g_dst[N_EDGES];
__device__ int   g_batch[N_NODES];

// packed f32x2 FMA (Blackwell-only; ptxas never emits this from C++)
__device__ __forceinline__ ull ffma2(ull a, ull b, ull c) {
    ull d;
    asm("fma.rn.f32x2 %0, %1, %2, %3;" : "=l"(d) : "l"(a), "l"(b), "l"(c));
    return d;
}
__device__ __forceinline__ ull dup2(float x) {
    unsigned u = __float_as_uint(x);
    return ((ull)u << 32) | (ull)u;
}
__device__ __forceinline__ float lo32(ull v) { return __uint_as_float((unsigned)v); }
__device__ __forceinline__ float hi32(ull v) { return __uint_as_float((unsigned)(v >> 32)); }

// ---------------------------------------------------------------------------
// prep: detect int32 vs int64 indices and convert into int32 scratch.
// Word (N_NODES-1) is ODD: under int64 layout it is a high half => 0;
// under int32 it is batch[N-1] = max graph id != 0.
// ---------------------------------------------------------------------------
__global__ void prep_kernel(const void* __restrict__ edge,
                            const void* __restrict__ batch) {
    const bool mode64 = (((const int*)batch)[N_NODES - 1] == 0);
    int t = blockIdx.x * blockDim.x + threadIdx.x;
    if (t < N_EDGES) {
        if (mode64) {
            g_src[t] = (int)((const long long*)edge)[t];
            g_dst[t] = (int)((const long long*)edge)[N_EDGES + t];
        } else {
            g_src[t] = ((const int*)edge)[t];
            g_dst[t] = ((const int*)edge)[N_EDGES + t];
        }
    }
    if (t < N_NODES) {
        g_batch[t] = mode64 ? (int)((const long long*)batch)[t]
                            : ((const int*)batch)[t];
    }
}

// ---------------------------------------------------------------------------
// Shared inner tile machinery: block tile 128x64, BK=32, 256 threads.
// A stored transposed As[k][row] (stride 132) -> row-pairs are LDS.64.
// W stored lane-duplicated Ws2[k][col] = (w,w) for f32x2.
// Per-thread tile: 8 rows (4 row-pairs) x 4 cols, acc packed as ull.
// ---------------------------------------------------------------------------
struct Tile {
    float As[32][132];
    ull   Ws2[32][64];
};

__device__ __forceinline__ void load_w_tile(Tile& s, const float* __restrict__ W,
                                            int k0, int tid) {
    #pragma unroll
    for (int sdx = 0; sdx < 2; ++sdx) {
        int idx = tid + sdx * 256;       // 0..511
        int k  = idx >> 4;               // 0..31
        int cg = (idx & 15) * 4;
        float4 w = *(const float4*)&W[(size_t)(k0 + k) * 64 + cg];
        s.Ws2[k][cg + 0] = dup2(w.x);
        s.Ws2[k][cg + 1] = dup2(w.y);
        s.Ws2[k][cg + 2] = dup2(w.z);
        s.Ws2[k][cg + 3] = dup2(w.w);
    }
}

__device__ __forceinline__ void mainloop(Tile& s, ull acc[4][4], int tx, int ty) {
    #pragma unroll
    for (int kk = 0; kk < 32; ++kk) {
        ull a2[4], w2[4];
        #pragma unroll
        for (int i = 0; i < 4; ++i)
            a2[i] = *(const ull*)&s.As[kk][ty * 8 + 2 * i];
        #pragma unroll
        for (int j = 0; j < 4; ++j)
            w2[j] = s.Ws2[kk][tx * 4 + j];
        #pragma unroll
        for (int i = 0; i < 4; ++i)
            #pragma unroll
            for (int j = 0; j < 4; ++j)
                acc[i][j] = ffma2(a2[i], w2[j], acc[i][j]);
    }
}

// ---------------------------------------------------------------------------
// GEMM 1 (plain): C[N,64] = A[N,K] @ W[K,64]   (K = 128 or 64)
// ---------------------------------------------------------------------------
template<int K>
__global__ __launch_bounds__(256) void mm_plain(const float* __restrict__ A,
                                                const float* __restrict__ W,
                                                float* __restrict__ C) {
    __shared__ Tile s;
    const int tid = threadIdx.x;
    const int tx = tid & 15;
    const int ty = tid >> 4;
    const int rowBase = blockIdx.x * 128;
    ull acc[4][4] = {};

    for (int k0 = 0; k0 < K; k0 += 32) {
        #pragma unroll
        for (int sdx = 0; sdx < 4; ++sdx) {
            int idx = tid + sdx * 256;
            int row = idx >> 3;
            int kg  = (idx & 7) * 4;
            float4 v = make_float4(0.f, 0.f, 0.f, 0.f);
            int gr = rowBase + row;
            if (gr < N_NODES)
                v = *(const float4*)&A[(size_t)gr * K + k0 + kg];
            s.As[kg + 0][row] = v.x; s.As[kg + 1][row] = v.y;
            s.As[kg + 2][row] = v.z; s.As[kg + 3][row] = v.w;
        }
        load_w_tile(s, W, k0, tid);
        __syncthreads();
        mainloop(s, acc, tx, ty);
        __syncthreads();
    }
    #pragma unroll
    for (int i = 0; i < 4; ++i) {
        int gr0 = rowBase + ty * 8 + 2 * i;
        if (gr0 < N_NODES)
            *(float4*)&C[(size_t)gr0 * 64 + tx * 4] =
                make_float4(lo32(acc[i][0]), lo32(acc[i][1]),
                            lo32(acc[i][2]), lo32(acc[i][3]));
        if (gr0 + 1 < N_NODES)
            *(float4*)&C[(size_t)(gr0 + 1) * 64 + tx * 4] =
                make_float4(hi32(acc[i][0]), hi32(acc[i][1]),
                            hi32(acc[i][2]), hi32(acc[i][3]));
    }
}

// ---------------------------------------------------------------------------
// GEMM 2 (fused): U = relu(Y + AGG + ba);  C = relu(U @ W + bb)   (K = 64)
// ---------------------------------------------------------------------------
__global__ __launch_bounds__(256) void mm_fused(const float* __restrict__ Y,
                                                const float* __restrict__ AGG,
                                                const float* __restrict__ ba,
                                                const float* __restrict__ W,
                                                const float* __restrict__ bb,
                                                float* __restrict__ C) {
    __shared__ Tile s;
    const int tid = threadIdx.x;
    const int tx = tid & 15;
    const int ty = tid >> 4;
    const int rowBase = blockIdx.x * 128;
    ull acc[4][4] = {};

    for (int k0 = 0; k0 < 64; k0 += 32) {
        #pragma unroll
        for (int sdx = 0; sdx < 4; ++sdx) {
            int idx = tid + sdx * 256;
            int row = idx >> 3;
            int kg  = (idx & 7) * 4;
            float4 v = make_float4(0.f, 0.f, 0.f, 0.f);
            int gr = rowBase + row;
            if (gr < N_NODES) {
                float4 y4 = *(const float4*)&Y  [(size_t)gr * 64 + k0 + kg];
                float4 a4 = *(const float4*)&AGG[(size_t)gr * 64 + k0 + kg];
                float4 b4 = *(const float4*)&ba[k0 + kg];
                v.x = fmaxf(y4.x + a4.x + b4.x, 0.f);
                v.y = fmaxf(y4.y + a4.y + b4.y, 0.f);
                v.z = fmaxf(y4.z + a4.z + b4.z, 0.f);
                v.w = fmaxf(y4.w + a4.w + b4.w, 0.f);
            }
            s.As[kg + 0][row] = v.x; s.As[kg + 1][row] = v.y;
            s.As[kg + 2][row] = v.z; s.As[kg + 3][row] = v.w;
        }
        load_w_tile(s, W, k0, tid);
        __syncthreads();
        mainloop(s, acc, tx, ty);
        __syncthreads();
    }
    float4 bbv = *(const float4*)&bb[tx * 4];
    float bbs[4] = {bbv.x, bbv.y, bbv.z, bbv.w};
    #pragma unroll
    for (int i = 0; i < 4; ++i) {
        int gr0 = rowBase + ty * 8 + 2 * i;
        if (gr0 < N_NODES) {
            float4 o;
            o.x = fmaxf(lo32(acc[i][0]) + bbs[0], 0.f);
            o.y = fmaxf(lo32(acc[i][1]) + bbs[1], 0.f);
            o.z = fmaxf(lo32(acc[i][2]) + bbs[2], 0.f);
            o.w = fmaxf(lo32(acc[i][3]) + bbs[3], 0.f);
            *(float4*)&C[(size_t)gr0 * 64 + tx * 4] = o;
        }
        if (gr0 + 1 < N_NODES) {
            float4 o;
            o.x = fmaxf(hi32(acc[i][0]) + bbs[0], 0.f);
            o.y = fmaxf(hi32(acc[i][1]) + bbs[1], 0.f);
            o.z = fmaxf(hi32(acc[i][2]) + bbs[2], 0.f);
            o.w = fmaxf(hi32(acc[i][3]) + bbs[3], 0.f);
            *(float4*)&C[(size_t)(gr0 + 1) * 64 + tx * 4] = o;
        }
    }
}

// ---------------------------------------------------------------------------
// Edge scatter: AGG[dst] += Y[src]  (16 threads per edge, float4 vector RED)
// ---------------------------------------------------------------------------
__global__ __launch_bounds__(256) void scatter_kernel(const float* __restrict__ Y,
                                                      float* __restrict__ AGG) {
    long long t = (long long)blockIdx.x * blockDim.x + threadIdx.x;
    if (t >= (long long)N_EDGES * 16) return;
    int e = (int)(t >> 4);
    int c = (int)(t & 15) * 4;
    int s = g_src[e];
    int d = g_dst[e];
    float4 v = *(const float4*)&Y[(size_t)s * 64 + c];
    atomicAdd((float4*)&AGG[(size_t)d * 64 + c], v);
}

// ---------------------------------------------------------------------------
// Head: per-graph pooled sum (batch sorted -> binary search node range),
// then relu(pooled@wh1+bh1)@wh2+bh2.  One 64-thread block per graph.
// ---------------------------------------------------------------------------
__global__ __launch_bounds__(64) void head_kernel(const float* __restrict__ H,
                                                  const float* __restrict__ wh1,
                                                  const float* __restrict__ bh1,
                                                  const float* __restrict__ wh2,
                                                  const float* __restrict__ bh2,
                                                  float* __restrict__ out) {
    const int g = blockIdx.x;
    const int tid = threadIdx.x;
    __shared__ float pooled[64];
    __shared__ float red[64];
    __shared__ int range[2];
    if (tid < 2) {
        int target = g + tid;
        int lo = 0, hi = N_NODES;
        while (lo < hi) {
            int mid = (lo + hi) >> 1;
            if (g_batch[mid] < target) lo = mid + 1; else hi = mid;
        }
        range[tid] = lo;
    }
    __syncthreads();
    const int lo = range[0], hi = range[1];
    float p = 0.f;
    for (int i = lo; i < hi; ++i) p += H[(size_t)i * 64 + tid];
    pooled[tid] = p;
    __syncthreads();
    float u = bh1[tid];
    #pragma unroll
    for (int k = 0; k < 64; ++k) u += pooled[k] * wh1[k * 64 + tid];
    u = fmaxf(u, 0.f);
    red[tid] = u * wh2[tid];
    __syncthreads();
    if (tid < 32) red[tid] += red[tid + 32];
    __syncthreads();
    if (tid < 32) {
        float v = red[tid];
        #pragma unroll
        for (int off = 16; off; off >>= 1)
            v += __shfl_down_sync(0xffffffffu, v, off);
        if (tid == 0) out[g] = v + bh2[0];
    }
}

// ---------------------------------------------------------------------------
extern "C" void kernel_launch(void* const* d_in, const int* in_sizes, int n_in,
                              void* d_out, int out_size) {
    const float* x    = (const float*)d_in[0];
    const void*  edge = d_in[1];
    const void*  batc = d_in[2];
    const float* wh1  = (const float*)d_in[15];
    const float* bh1  = (const float*)d_in[16];
    const float* wh2  = (const float*)d_in[17];
    const float* bh2  = (const float*)d_in[18];

    float *yb, *aggb, *hb;
    cudaGetSymbolAddress((void**)&yb,   g_y);
    cudaGetSymbolAddress((void**)&aggb, g_agg);
    cudaGetSymbolAddress((void**)&hb,   g_h);

    const int mmGrid   = (N_NODES + 127) / 128;
    const int scatGrid = (int)(((long long)N_EDGES * 16 + 255) / 256);
    const size_t aggBytes = (size_t)N_NODES * HID * sizeof(float);

    prep_kernel<<<(N_EDGES + 255) / 256, 256>>>(edge, batc);

    for (int L = 0; L < 3; ++L) {
        const float* wa = (const float*)d_in[3 + 4 * L];
        const float* ba = (const float*)d_in[4 + 4 * L];
        const float* wb = (const float*)d_in[5 + 4 * L];
        const float* bb = (const float*)d_in[6 + 4 * L];
        if (L == 0) mm_plain<128><<<mmGrid, 256>>>(x,  wa, yb);
        else        mm_plain< 64><<<mmGrid, 256>>>(hb, wa, yb);
        cudaMemsetAsync(aggb, 0, aggBytes);
        scatter_kernel<<<scatGrid, 256>>>(yb, aggb);
        mm_fused<<<mmGrid, 256>>>(yb, aggb, ba, wb, bb, hb);
    }
    head_kernel<<<N_GRAPHS, 64>>>(hb, wh1, bh1, wh2, bh2, (float*)d_out);
}

// round 7
// speedup vs baseline: 1.6779x; 1.6779x over previous
#include <cuda_runtime.h>
#include <cstdint>

#define N_NODES 500000
#define N_EDGES 1250000
#define IN_DIM  128
#define HID     64
#define N_GRAPHS 16384

// ---- scratch (static device globals: allocation-free rule) ----
__device__ float g_y  [(size_t)N_NODES * HID];
__device__ float g_agg[(size_t)N_NODES * HID];
__device__ float g_h  [(size_t)N_NODES * HID];
__device__ int   g_src[N_EDGES];
__device__ int   g_dst[N_EDGES];
__device__ int   g_batch[N_NODES];

// ---------------------------------------------------------------------------
// tf32 helpers
// ---------------------------------------------------------------------------
__device__ __forceinline__ float f2tf32(float x) {
    unsigned r;
    asm("cvt.rna.tf32.f32 %0, %1;" : "=r"(r) : "f"(x));
    return __uint_as_float(r);
}
__device__ __forceinline__ void mma_tf32(float& c0, float& c1, float& c2, float& c3,
                                         unsigned a0, unsigned a1, unsigned a2, unsigned a3,
                                         unsigned b0, unsigned b1) {
    asm volatile("mma.sync.aligned.m16n8k8.row.col.f32.tf32.tf32.f32 "
                 "{%0,%1,%2,%3}, {%4,%5,%6,%7}, {%8,%9}, {%0,%1,%2,%3};"
                 : "+f"(c0), "+f"(c1), "+f"(c2), "+f"(c3)
                 : "r"(a0), "r"(a1), "r"(a2), "r"(a3), "r"(b0), "r"(b1));
}

// ---------------------------------------------------------------------------
// prep: detect int32 vs int64 indices and convert into int32 scratch.
// Word (N_NODES-1) is ODD: under int64 layout it is a high half => 0;
// under int32 it is batch[N-1] = max graph id != 0.
// ---------------------------------------------------------------------------
__global__ void prep_kernel(const void* __restrict__ edge,
                            const void* __restrict__ batch) {
    const bool mode64 = (((const int*)batch)[N_NODES - 1] == 0);
    int t = blockIdx.x * blockDim.x + threadIdx.x;
    if (t < N_EDGES) {
        if (mode64) {
            g_src[t] = (int)((const long long*)edge)[t];
            g_dst[t] = (int)((const long long*)edge)[N_EDGES + t];
        } else {
            g_src[t] = ((const int*)edge)[t];
            g_dst[t] = ((const int*)edge)[N_EDGES + t];
        }
    }
    if (t < N_NODES) {
        g_batch[t] = mode64 ? (int)((const long long*)batch)[t]
                            : ((const int*)batch)[t];
    }
}

// ---------------------------------------------------------------------------
// Tensor-core GEMM machinery.
// Block tile 128 (rows) x 64 (cols), BK=32, 256 threads = 8 warps.
// Warp w: rows (w&3)*32..+31, cols (w>>2)*32..+31.  m16n8k8 tf32 mma:
// per k-step of 8 -> 2 m-tiles x 4 n-tiles = 8 mma.
// As[row][36]: fragment bank = (4g+tg) -> conflict-free.
// Ws[k][72]:   fragment bank = (8tg+g) -> conflict-free.
// Values stored already converted to tf32 (cvt.rna at staging time).
// ---------------------------------------------------------------------------
#define AS_STRIDE 36
#define WS_STRIDE 72

struct SmemT {
    float As[128][AS_STRIDE];
    float Ws[32][WS_STRIDE];
};

__device__ __forceinline__ void load_w_chunk(SmemT& s, const float* __restrict__ W,
                                             int k0, int tid) {
    #pragma unroll
    for (int sdx = 0; sdx < 2; ++sdx) {
        int idx = tid + sdx * 256;            // 0..511 float4 slots
        int k  = idx >> 4;                    // 0..31
        int cg = (idx & 15) * 4;
        float4 w = *(const float4*)&W[(size_t)(k0 + k) * 64 + cg];
        w.x = f2tf32(w.x); w.y = f2tf32(w.y);
        w.z = f2tf32(w.z); w.w = f2tf32(w.w);
        *(float4*)&s.Ws[k][cg] = w;
    }
}

__device__ __forceinline__ void mma_chunk(SmemT& s, float c[2][4][4],
                                          int wrow, int wcol, int g, int tg) {
    #pragma unroll
    for (int kk = 0; kk < 32; kk += 8) {
        unsigned a[2][4], b[4][2];
        #pragma unroll
        for (int i = 0; i < 2; ++i) {
            int r0 = wrow + 16 * i + g;
            a[i][0] = __float_as_uint(s.As[r0    ][kk + tg]);
            a[i][1] = __float_as_uint(s.As[r0 + 8][kk + tg]);
            a[i][2] = __float_as_uint(s.As[r0    ][kk + tg + 4]);
            a[i][3] = __float_as_uint(s.As[r0 + 8][kk + tg + 4]);
        }
        #pragma unroll
        for (int j = 0; j < 4; ++j) {
            int cc = wcol + 8 * j + g;
            b[j][0] = __float_as_uint(s.Ws[kk + tg    ][cc]);
            b[j][1] = __float_as_uint(s.Ws[kk + tg + 4][cc]);
        }
        #pragma unroll
        for (int i = 0; i < 2; ++i)
            #pragma unroll
            for (int j = 0; j < 4; ++j)
                mma_tf32(c[i][j][0], c[i][j][1], c[i][j][2], c[i][j][3],
                         a[i][0], a[i][1], a[i][2], a[i][3],
                         b[j][0], b[j][1]);
    }
}

// ---------------------------------------------------------------------------
// GEMM 1 (plain): C[N,64] = A[N,K] @ W[K,64]   (K = 128 or 64)
// ---------------------------------------------------------------------------
template<int K>
__global__ __launch_bounds__(256) void mm_plain(const float* __restrict__ A,
                                                const float* __restrict__ W,
                                                float* __restrict__ C) {
    __shared__ SmemT s;
    const int tid  = threadIdx.x;
    const int lane = tid & 31;
    const int w    = tid >> 5;
    const int g    = lane >> 2;
    const int tg   = lane & 3;
    const int wrow = (w & 3) * 32;
    const int wcol = (w >> 2) * 32;
    const int rowBase = blockIdx.x * 128;
    float c[2][4][4] = {};

    for (int k0 = 0; k0 < K; k0 += 32) {
        #pragma unroll
        for (int sdx = 0; sdx < 4; ++sdx) {
            int idx = tid + sdx * 256;        // 0..1023 float4 slots
            int row = idx >> 3;
            int kg  = (idx & 7) * 4;
            float4 v = make_float4(0.f, 0.f, 0.f, 0.f);
            int gr = rowBase + row;
            if (gr < N_NODES)
                v = *(const float4*)&A[(size_t)gr * K + k0 + kg];
            v.x = f2tf32(v.x); v.y = f2tf32(v.y);
            v.z = f2tf32(v.z); v.w = f2tf32(v.w);
            *(float4*)&s.As[row][kg] = v;
        }
        load_w_chunk(s, W, k0, tid);
        __syncthreads();
        mma_chunk(s, c, wrow, wcol, g, tg);
        __syncthreads();
    }
    #pragma unroll
    for (int i = 0; i < 2; ++i) {
        int r0 = rowBase + wrow + 16 * i + g;
        #pragma unroll
        for (int j = 0; j < 4; ++j) {
            int col = wcol + 8 * j + 2 * tg;
            if (r0 < N_NODES)
                *(float2*)&C[(size_t)r0 * 64 + col] = make_float2(c[i][j][0], c[i][j][1]);
            if (r0 + 8 < N_NODES)
                *(float2*)&C[(size_t)(r0 + 8) * 64 + col] = make_float2(c[i][j][2], c[i][j][3]);
        }
    }
}

// ---------------------------------------------------------------------------
// GEMM 2 (fused): U = relu(Y + AGG + ba);  C = relu(U @ W + bb)   (K = 64)
// ---------------------------------------------------------------------------
__global__ __launch_bounds__(256) void mm_fused(const float* __restrict__ Y,
                                                const float* __restrict__ AGG,
                                                const float* __restrict__ ba,
                                                const float* __restrict__ W,
                                                const float* __restrict__ bb,
                                                float* __restrict__ C) {
    __shared__ SmemT s;
    const int tid  = threadIdx.x;
    const int lane = tid & 31;
    const int w    = tid >> 5;
    const int g    = lane >> 2;
    const int tg   = lane & 3;
    const int wrow = (w & 3) * 32;
    const int wcol = (w >> 2) * 32;
    const int rowBase = blockIdx.x * 128;
    float c[2][4][4] = {};

    for (int k0 = 0; k0 < 64; k0 += 32) {
        #pragma unroll
        for (int sdx = 0; sdx < 4; ++sdx) {
            int idx = tid + sdx * 256;
            int row = idx >> 3;
            int kg  = (idx & 7) * 4;
            float4 v = make_float4(0.f, 0.f, 0.f, 0.f);
            int gr = rowBase + row;
            if (gr < N_NODES) {
                float4 y4 = *(const float4*)&Y  [(size_t)gr * 64 + k0 + kg];
                float4 a4 = *(const float4*)&AGG[(size_t)gr * 64 + k0 + kg];
                float4 b4 = *(const float4*)&ba[k0 + kg];
                v.x = f2tf32(fmaxf(y4.x + a4.x + b4.x, 0.f));
                v.y = f2tf32(fmaxf(y4.y + a4.y + b4.y, 0.f));
                v.z = f2tf32(fmaxf(y4.z + a4.z + b4.z, 0.f));
                v.w = f2tf32(fmaxf(y4.w + a4.w + b4.w, 0.f));
            }
            *(float4*)&s.As[row][kg] = v;
        }
        load_w_chunk(s, W, k0, tid);
        __syncthreads();
        mma_chunk(s, c, wrow, wcol, g, tg);
        __syncthreads();
    }
    #pragma unroll
    for (int i = 0; i < 2; ++i) {
        int r0 = rowBase + wrow + 16 * i + g;
        #pragma unroll
        for (int j = 0; j < 4; ++j) {
            int col = wcol + 8 * j + 2 * tg;
            float b0 = bb[col], b1 = bb[col + 1];
            if (r0 < N_NODES)
                *(float2*)&C[(size_t)r0 * 64 + col] =
                    make_float2(fmaxf(c[i][j][0] + b0, 0.f), fmaxf(c[i][j][1] + b1, 0.f));
            if (r0 + 8 < N_NODES)
                *(float2*)&C[(size_t)(r0 + 8) * 64 + col] =
                    make_float2(fmaxf(c[i][j][2] + b0, 0.f), fmaxf(c[i][j][3] + b1, 0.f));
        }
    }
}

// ---------------------------------------------------------------------------
// Edge scatter: AGG[dst] += Y[src]  (16 threads per edge, float4 vector RED)
// ---------------------------------------------------------------------------
__global__ __launch_bounds__(256) void scatter_kernel(const float* __restrict__ Y,
                                                      float* __restrict__ AGG) {
    long long t = (long long)blockIdx.x * blockDim.x + threadIdx.x;
    if (t >= (long long)N_EDGES * 16) return;
    int e = (int)(t >> 4);
    int c = (int)(t & 15) * 4;
    int s = g_src[e];
    int d = g_dst[e];
    float4 v = *(const float4*)&Y[(size_t)s * 64 + c];
    atomicAdd((float4*)&AGG[(size_t)d * 64 + c], v);
}

// ---------------------------------------------------------------------------
// Head: per-graph pooled sum (batch sorted -> binary search node range),
// then relu(pooled@wh1+bh1)@wh2+bh2.  One 64-thread block per graph.
// ---------------------------------------------------------------------------
__global__ __launch_bounds__(64) void head_kernel(const float* __restrict__ H,
                                                  const float* __restrict__ wh1,
                                                  const float* __restrict__ bh1,
                                                  const float* __restrict__ wh2,
                                                  const float* __restrict__ bh2,
                                                  float* __restrict__ out) {
    const int g = blockIdx.x;
    const int tid = threadIdx.x;
    __shared__ float pooled[64];
    __shared__ float red[64];
    __shared__ int range[2];
    if (tid < 2) {
        int target = g + tid;
        int lo = 0, hi = N_NODES;
        while (lo < hi) {
            int mid = (lo + hi) >> 1;
            if (g_batch[mid] < target) lo = mid + 1; else hi = mid;
        }
        range[tid] = lo;
    }
    __syncthreads();
    const int lo = range[0], hi = range[1];
    float p = 0.f;
    for (int i = lo; i < hi; ++i) p += H[(size_t)i * 64 + tid];
    pooled[tid] = p;
    __syncthreads();
    float u = bh1[tid];
    #pragma unroll
    for (int k = 0; k < 64; ++k) u += pooled[k] * wh1[k * 64 + tid];
    u = fmaxf(u, 0.f);
    red[tid] = u * wh2[tid];
    __syncthreads();
    if (tid < 32) red[tid] += red[tid + 32];
    __syncthreads();
    if (tid < 32) {
        float v = red[tid];
        #pragma unroll
        for (int off = 16; off; off >>= 1)
            v += __shfl_down_sync(0xffffffffu, v, off);
        if (tid == 0) out[g] = v + bh2[0];
    }
}

// ---------------------------------------------------------------------------
extern "C" void kernel_launch(void* const* d_in, const int* in_sizes, int n_in,
                              void* d_out, int out_size) {
    const float* x    = (const float*)d_in[0];
    const void*  edge = d_in[1];
    const void*  batc = d_in[2];
    const float* wh1  = (const float*)d_in[15];
    const float* bh1  = (const float*)d_in[16];
    const float* wh2  = (const float*)d_in[17];
    const float* bh2  = (const float*)d_in[18];

    float *yb, *aggb, *hb;
    cudaGetSymbolAddress((void**)&yb,   g_y);
    cudaGetSymbolAddress((void**)&aggb, g_agg);
    cudaGetSymbolAddress((void**)&hb,   g_h);

    const int mmGrid   = (N_NODES + 127) / 128;
    const int scatGrid = (int)(((long long)N_EDGES * 16 + 255) / 256);
    const size_t aggBytes = (size_t)N_NODES * HID * sizeof(float);

    prep_kernel<<<(N_EDGES + 255) / 256, 256>>>(edge, batc);

    for (int L = 0; L < 3; ++L) {
        const float* wa = (const float*)d_in[3 + 4 * L];
        const float* ba = (const float*)d_in[4 + 4 * L];
        const float* wb = (const float*)d_in[5 + 4 * L];
        const float* bb = (const float*)d_in[6 + 4 * L];
        if (L == 0) mm_plain<128><<<mmGrid, 256>>>(x,  wa, yb);
        else        mm_plain< 64><<<mmGrid, 256>>>(hb, wa, yb);
        cudaMemsetAsync(aggb, 0, aggBytes);
        scatter_kernel<<<scatGrid, 256>>>(yb, aggb);
        mm_fused<<<mmGrid, 256>>>(yb, aggb, ba, wb, bb, hb);
    }
    head_kernel<<<N_GRAPHS, 64>>>(hb, wh1, bh1, wh2, bh2, (float*)d_out);
}